// round 12
// baseline (speedup 1.0000x reference)
#include <cuda_runtime.h>
#include <cstdint>

// Conv4D via mma.sync tf32 (portable sm_80+ PTX).
// x(8,16,32,24,24,24) NCLDHW * W(32,16,3,3,3,3) OILDHW -> out(8,32,30,22,22,22), +3*b.
//
// R12: each CTA computes TWO adjacent d_out (d0, d0+1). The 18 logical (lk,dk)
// slabs collapse to 12 unique (lk, d_in) x-slabs; A fragments shared between
// both outputs. W staged per-lk (3 dk tiles, 54KB), double-buffered by lk parity.
// Cuts cp.async issue (the R7-R11 bottleneck) by ~40% per output.

#define OFF_X0 0
#define OFF_X1 37120               // 580 rows * 64B
#define OFF_W0 74240               // 3 dk tiles * 18432B = 55296
#define OFF_W1 129536
#define OFF_BS 184832
#define SMEM_TOTAL 184960

#define L_STRIDE 13824             // 24*24*24
#define OUT_CO_STRIDE 319440       // 30*22*22*22

__device__ uint32_t g_xp[56623104];    // [n][l][d][m=576][16 ci quad-interleaved]
__device__ uint32_t g_wp[41472];       // [s=lk*3+dk][tap][co][16 ci quad-interleaved]

static __device__ __forceinline__ uint32_t s2u(const void* p) {
    uint32_t a;
    asm("{ .reg .u64 t; cvta.to.shared.u64 t, %1; cvt.u32.u64 %0, t; }" : "=r"(a) : "l"(p));
    return a;
}
static __device__ __forceinline__ uint32_t tf32rn(float f) {
    uint32_t o;
    asm("cvt.rna.tf32.f32 %0, %1;" : "=r"(o) : "f"(f));
    return o;
}
static __device__ __forceinline__ void cp16(uint32_t dst, const void* src) {
    asm volatile("cp.async.cg.shared.global [%0], [%1], 16;" :: "r"(dst), "l"(src) : "memory");
}
static __device__ __forceinline__ void lds4(uint32_t& r0, uint32_t& r1, uint32_t& r2, uint32_t& r3, uint32_t a) {
    asm volatile("ld.shared.v4.u32 {%0,%1,%2,%3}, [%4];" : "=r"(r0), "=r"(r1), "=r"(r2), "=r"(r3) : "r"(a));
}

#define MMA_TF32(d, a0, a1, a2, a3, b0, b1) \
    asm volatile("mma.sync.aligned.m16n8k8.row.col.f32.tf32.tf32.f32 " \
        "{%0,%1,%2,%3}, {%4,%5,%6,%7}, {%8,%9}, {%0,%1,%2,%3};" \
        : "+f"((d)[0]), "+f"((d)[1]), "+f"((d)[2]), "+f"((d)[3]) \
        : "r"(a0), "r"(a1), "r"(a2), "r"(a3), "r"(b0), "r"(b1))

// ---- prepass: x -> tf32 bits; within-row order pos = (ci%4)*4 + ci/4 ----
__global__ __launch_bounds__(256)
void prep_x_kernel(const float* __restrict__ x) {
    const int d = blockIdx.x, l = blockIdx.y, n = blockIdx.z;
    const int tid = threadIdx.x;
    const size_t src0 = ((size_t)(n * 16) * 32 + l) * L_STRIDE + d * 576;
    uint32_t* dst0 = g_xp + (((size_t)(n * 32 + l) * 24 + d) * 576) * 16;
    for (int m = tid; m < 576; m += 256) {
        uint32_t v[16];
        #pragma unroll
        for (int ci = 0; ci < 16; ci++)
            v[(ci & 3) * 4 + (ci >> 2)] = tf32rn(x[src0 + (size_t)ci * (32 * L_STRIDE) + m]);
        uint32_t* dr = dst0 + m * 16;
        #pragma unroll
        for (int q = 0; q < 4; q++)
            *(uint4*)(dr + q * 4) = make_uint4(v[q*4], v[q*4+1], v[q*4+2], v[q*4+3]);
    }
}

// ---- prepass: W -> tf32 bits, [s][tap][co][pos], ci = (pos>>2) + (pos&3)*4 ----
__global__ __launch_bounds__(256)
void prep_w_kernel(const float* __restrict__ W) {
    int e = blockIdx.x * 256 + threadIdx.x;     // 0..41471
    int pos = e & 15;
    int co  = (e >> 4) & 31;
    int t9  = e >> 9;                            // s*9+tap
    int s   = t9 / 9, tap = t9 - 9 * s;
    int lk = s / 3,  dk = s - 3 * lk;
    int hk = tap / 3, wk = tap - 3 * hk;
    int ci = (pos >> 2) + (pos & 3) * 4;
    g_wp[e] = tf32rn(W[(size_t)(co * 16 + ci) * 81 + lk * 27 + dk * 9 + hk * 3 + wk]);
}

extern __shared__ char smem[];

__global__ __launch_bounds__(384)
void conv4d_mma_kernel(const float* __restrict__ b, float* __restrict__ out)
{
    const int d0    = blockIdx.x * 2;   // d_out pair (d0, d0+1), bx 0..10
    const int l_out = blockIdx.y;       // 0..29
    const int n     = blockIdx.z;       // 0..7
    const int tid   = threadIdx.x;
    const int wid   = tid >> 5;         // 0..11
    const int lid   = tid & 31;
    const int c     = lid & 3;
    const int g     = lid >> 2;
    const uint32_t sb = s2u(smem);

    if (tid < 32) ((float*)(smem + OFF_BS))[tid] = 3.0f * b[tid];

    // stage x slab k (lk = k/4, d_in = d0 + k%4) into buffer k&1
    auto stage_x = [&](int k) {
        const int lk = k >> 2, j = k & 3;
        const uint32_t xo = sb + ((k & 1) ? OFF_X1 : OFF_X0);
        const uint32_t* xs = g_xp + (((size_t)(n * 32 + (l_out + lk)) * 24 + (d0 + j)) * 576) * 16;
        #pragma unroll
        for (int j6 = 0; j6 < 6; j6++) {
            int e = tid + j6 * 384;              // 0..2303
            cp16(xo + (uint32_t)(e * 16), xs + (size_t)e * 4);
        }
    };
    // stage all 3 dk tiles of W for lk into buffer lk&1
    auto stage_w = [&](int lk) {
        const uint32_t wo = sb + ((lk & 1) ? OFF_W1 : OFF_W0);
        const uint32_t* wsrc = g_wp + lk * 13824;
        #pragma unroll
        for (int j9 = 0; j9 < 9; j9++) {
            int e = tid + j9 * 384;              // 0..3455
            cp16(wo + (uint32_t)(e * 16), wsrc + (size_t)e * 4);
        }
    };

    const int cnt = (wid < 9) ? 3 : 2;           // m-tiles: t = wid + 12*mt, 33 tiles

    float acc[2][3][4][4];
    #pragma unroll
    for (int o = 0; o < 2; o++)
        #pragma unroll
        for (int mt = 0; mt < 3; mt++)
            #pragma unroll
            for (int nt = 0; nt < 4; nt++)
                #pragma unroll
                for (int q = 0; q < 4; q++)
                    acc[o][mt][nt][q] = 0.0f;

    stage_x(0); stage_w(0);
    asm volatile("cp.async.commit_group;" ::: "memory");

    for (int k = 0; k < 12; k++) {
        const int lk = k >> 2, j = k & 3;
        if (k < 11) {
            stage_x(k + 1);
            if (j == 0 && lk < 2) stage_w(lk + 1);
            asm volatile("cp.async.commit_group;" ::: "memory");
            asm volatile("cp.async.wait_group 1;" ::: "memory");
        } else {
            asm volatile("cp.async.wait_group 0;" ::: "memory");
        }
        __syncthreads();

        const uint32_t xb = sb + ((k & 1) ? OFF_X1 : OFF_X0);
        const uint32_t wb = sb + ((lk & 1) ? OFF_W1 : OFF_W0);
        const bool v0 = (j <= 2);                // output o=0 uses dk=j
        const bool v1 = (j >= 1);                // output o=1 uses dk=j-1
        const uint32_t wb0 = wb + (uint32_t)(j * 18432);
        const uint32_t wb1 = wb + (uint32_t)((j - 1) * 18432);

        #pragma unroll
        for (int tap = 0; tap < 9; tap++) {
            const int hk = tap / 3;
            const int tapoff = hk * 24 + (tap - 3 * hk);
            const uint32_t wrowoff = (uint32_t)(((tap * 32 + g) * 16 + c * 4) * 4);
            uint32_t b0[4][4], b1[4][4];
            if (v0) {
                #pragma unroll
                for (int nt = 0; nt < 4; nt++)
                    lds4(b0[0][nt], b0[1][nt], b0[2][nt], b0[3][nt],
                         wb0 + wrowoff + nt * (8 * 64));
            }
            if (v1) {
                #pragma unroll
                for (int nt = 0; nt < 4; nt++)
                    lds4(b1[0][nt], b1[1][nt], b1[2][nt], b1[3][nt],
                         wb1 + wrowoff + nt * (8 * 64));
            }
            const uint32_t xrow = xb + (uint32_t)(((g + tapoff) * 16 + c * 4) * 4);
            #pragma unroll
            for (int mt = 0; mt < 3; mt++) {
                if (mt >= cnt) break;
                const int m0 = (wid + 12 * mt) * 16;
                uint32_t l0, l1, l2, l3, h0, h1, h2, h3;
                lds4(l0, l1, l2, l3, xrow + m0 * 64);
                lds4(h0, h1, h2, h3, xrow + (m0 + 8) * 64);
                if (v0) {
                    #pragma unroll
                    for (int nt = 0; nt < 4; nt++)
                        MMA_TF32(acc[0][mt][nt], l0, h0, l1, h1, b0[0][nt], b0[1][nt]);
                    #pragma unroll
                    for (int nt = 0; nt < 4; nt++)
                        MMA_TF32(acc[0][mt][nt], l2, h2, l3, h3, b0[2][nt], b0[3][nt]);
                }
                if (v1) {
                    #pragma unroll
                    for (int nt = 0; nt < 4; nt++)
                        MMA_TF32(acc[1][mt][nt], l0, h0, l1, h1, b1[0][nt], b1[1][nt]);
                    #pragma unroll
                    for (int nt = 0; nt < 4; nt++)
                        MMA_TF32(acc[1][mt][nt], l2, h2, l3, h3, b1[2][nt], b1[3][nt]);
                }
            }
        }
        __syncthreads();
    }

    // ---- epilogue: two d_out outputs ----
    const float* bs = (const float*)(smem + OFF_BS);
    #pragma unroll
    for (int o = 0; o < 2; o++) {
        const int spat = l_out * 10648 + (d0 + o) * 484;
        for (int mt = 0; mt < cnt; mt++) {
            const int mb = (wid + 12 * mt) * 16 + g;
            #pragma unroll
            for (int hm = 0; hm < 2; hm++) {
                int m = mb + 8 * hm;
                int h = m / 24;
                int w = m - 24 * h;
                if (h < 22 && w < 22) {
                    size_t pos = (size_t)spat + h * 22 + w;
                    #pragma unroll
                    for (int nt = 0; nt < 4; nt++) {
                        #pragma unroll
                        for (int hc = 0; hc < 2; hc++) {
                            int co = nt * 8 + 2 * c + hc;
                            out[(size_t)(n * 32 + co) * OUT_CO_STRIDE + pos] =
                                acc[o][mt][nt][hm * 2 + hc] + bs[co];
                        }
                    }
                }
            }
        }
    }
}

extern "C" void kernel_launch(void* const* d_in, const int* in_sizes, int n_in,
                              void* d_out, int out_size)
{
    const float* x = (const float*)d_in[0];
    const float* W = (const float*)d_in[1];
    const float* b = (const float*)d_in[2];
    float* out = (float*)d_out;

    dim3 pgrid(24, 32, 8);
    prep_x_kernel<<<pgrid, 256>>>(x);
    prep_w_kernel<<<162, 256>>>(W);

    cudaFuncSetAttribute(conv4d_mma_kernel,
                         cudaFuncAttributeMaxDynamicSharedMemorySize, SMEM_TOTAL);
    dim3 grid(11, 30, 8);   // (d_out pair, l_out, n)
    conv4d_mma_kernel<<<grid, 384, SMEM_TOTAL>>>(b, out);
}

// round 15
// speedup vs baseline: 1.0928x; 1.0928x over previous
#include <cuda_runtime.h>
#include <cstdint>

// Conv4D via mma.sync tf32 (portable sm_80+ PTX).
// x(8,16,32,24,24,24) NCLDHW * W(32,16,3,3,3,3) OILDHW -> out(8,32,30,22,22,22), +3*b.
//
// R13 = R11 (384 thr / 12 warps, k-quad lds4 layout, register-pipelined taps)
// with TRIPLE-buffered x and W staging: one __syncthreads per slab instead of
// two (stage(s+2) writes buf (s+2)%3 while buf s%3 is read -> no WAR hazard).

#define XB 37120                   // 580 rows * 64B per x buffer
#define WB 18432                   // 288 rows * 64B per W buffer
#define OFF_X 0                    // 3 buffers
#define OFF_W (3 * XB)             // 111360, 3 buffers
#define OFF_BS (OFF_W + 3 * WB)    // 166656
#define SMEM_TOTAL (OFF_BS + 128)  // 166784

#define L_STRIDE 13824             // 24*24*24
#define OUT_CO_STRIDE 319440       // 30*22*22*22

__device__ uint32_t g_xp[56623104];    // [n][l][d][m=576][16 ci quad-interleaved]
__device__ uint32_t g_wp[41472];       // [s][tap][co][16 ci quad-interleaved]

static __device__ __forceinline__ uint32_t s2u(const void* p) {
    uint32_t a;
    asm("{ .reg .u64 t; cvta.to.shared.u64 t, %1; cvt.u32.u64 %0, t; }" : "=r"(a) : "l"(p));
    return a;
}
static __device__ __forceinline__ uint32_t tf32rn(float f) {
    uint32_t o;
    asm("cvt.rna.tf32.f32 %0, %1;" : "=r"(o) : "f"(f));
    return o;
}
static __device__ __forceinline__ void cp16(uint32_t dst, const void* src) {
    asm volatile("cp.async.cg.shared.global [%0], [%1], 16;" :: "r"(dst), "l"(src) : "memory");
}
static __device__ __forceinline__ void lds4(uint32_t& r0, uint32_t& r1, uint32_t& r2, uint32_t& r3, uint32_t a) {
    asm volatile("ld.shared.v4.u32 {%0,%1,%2,%3}, [%4];" : "=r"(r0), "=r"(r1), "=r"(r2), "=r"(r3) : "r"(a));
}

#define MMA_TF32(d, a0, a1, a2, a3, b0, b1) \
    asm volatile("mma.sync.aligned.m16n8k8.row.col.f32.tf32.tf32.f32 " \
        "{%0,%1,%2,%3}, {%4,%5,%6,%7}, {%8,%9}, {%0,%1,%2,%3};" \
        : "+f"((d)[0]), "+f"((d)[1]), "+f"((d)[2]), "+f"((d)[3]) \
        : "r"(a0), "r"(a1), "r"(a2), "r"(a3), "r"(b0), "r"(b1))

// ---- prepass: x -> tf32 bits; within-row order pos = (ci%4)*4 + ci/4 ----
__global__ __launch_bounds__(256)
void prep_x_kernel(const float* __restrict__ x) {
    const int d = blockIdx.x, l = blockIdx.y, n = blockIdx.z;
    const int tid = threadIdx.x;
    const size_t src0 = ((size_t)(n * 16) * 32 + l) * L_STRIDE + d * 576;
    uint32_t* dst0 = g_xp + (((size_t)(n * 32 + l) * 24 + d) * 576) * 16;
    for (int m = tid; m < 576; m += 256) {
        uint32_t v[16];
        #pragma unroll
        for (int ci = 0; ci < 16; ci++)
            v[(ci & 3) * 4 + (ci >> 2)] = tf32rn(x[src0 + (size_t)ci * (32 * L_STRIDE) + m]);
        uint32_t* dr = dst0 + m * 16;
        #pragma unroll
        for (int q = 0; q < 4; q++)
            *(uint4*)(dr + q * 4) = make_uint4(v[q*4], v[q*4+1], v[q*4+2], v[q*4+3]);
    }
}

// ---- prepass: W -> tf32 bits, [s][tap][co][pos], ci = (pos>>2) + (pos&3)*4 ----
__global__ __launch_bounds__(256)
void prep_w_kernel(const float* __restrict__ W) {
    int e = blockIdx.x * 256 + threadIdx.x;     // 0..41471
    int pos = e & 15;
    int co  = (e >> 4) & 31;
    int t9  = e >> 9;                            // s*9+tap
    int s   = t9 / 9, tap = t9 - 9 * s;
    int lk = s / 3,  dk = s - 3 * lk;
    int hk = tap / 3, wk = tap - 3 * hk;
    int ci = (pos >> 2) + (pos & 3) * 4;
    g_wp[e] = tf32rn(W[(size_t)(co * 16 + ci) * 81 + lk * 27 + dk * 9 + hk * 3 + wk]);
}

extern __shared__ char smem[];

__global__ __launch_bounds__(384)
void conv4d_mma_kernel(const float* __restrict__ b, float* __restrict__ out)
{
    const int d_out = blockIdx.x;   // 0..21
    const int l_out = blockIdx.y;   // 0..29
    const int n     = blockIdx.z;   // 0..7
    const int tid   = threadIdx.x;
    const int wid   = tid >> 5;     // 0..11
    const int lid   = tid & 31;
    const int c     = lid & 3;
    const int g     = lid >> 2;
    const uint32_t sb = s2u(smem);

    if (tid < 32) ((float*)(smem + OFF_BS))[tid] = 3.0f * b[tid];

    // stage slab s into buffer s%3 (x and W, one commit group)
    auto stage = [&](int s) {
        const int bi = s % 3;
        const int lk = s / 3, dk = s - 3 * lk;
        const uint32_t xo = sb + OFF_X + bi * XB;
        const uint32_t wo = sb + OFF_W + bi * WB;
        const uint32_t* xs = g_xp + (((size_t)(n * 32 + (l_out + lk)) * 24 + (d_out + dk)) * 576) * 16;
        #pragma unroll
        for (int j6 = 0; j6 < 6; j6++) {
            int j = tid + j6 * 384;              // 0..2303
            cp16(xo + (uint32_t)(j * 16), xs + (size_t)j * 4);
        }
        const uint32_t* wsrc = g_wp + s * 4608;
        #pragma unroll
        for (int j3 = 0; j3 < 3; j3++) {
            int j = tid + j3 * 384;              // 0..1151
            cp16(wo + (uint32_t)(j * 16), wsrc + j * 4);
        }
        asm volatile("cp.async.commit_group;" ::: "memory");
    };

    const int cnt = (wid < 9) ? 3 : 2;           // tiles: t = wid + 12*mt, 33 tiles

    float acc[3][4][4];
    #pragma unroll
    for (int mt = 0; mt < 3; mt++)
        #pragma unroll
        for (int nt = 0; nt < 4; nt++)
            #pragma unroll
            for (int q = 0; q < 4; q++)
                acc[mt][nt][q] = 0.0f;

    stage(0);
    stage(1);

    uint32_t wreg[2][4][4];   // [buf][q][nt]
    uint32_t areg[2][3][8];   // [buf][mt][l0..l3,h0..h3]

    for (int s = 0; s < 9; s++) {
        const int bi = s % 3;
        if (s < 7) {
            stage(s + 2);
            asm volatile("cp.async.wait_group 2;" ::: "memory");   // slab s done
        } else if (s == 7) {
            asm volatile("cp.async.wait_group 1;" ::: "memory");   // slab 7 done
        } else {
            asm volatile("cp.async.wait_group 0;" ::: "memory");   // slab 8 done
        }
        __syncthreads();   // single barrier per slab (no end-of-slab barrier:
                           // stage(s+2) writes buf (s+2)%3, never buf s%3)

        const uint32_t xb = sb + OFF_X + bi * XB;
        const uint32_t wb = sb + OFF_W + bi * WB;

        auto loadB = [&](int tap, uint32_t w[4][4]) {
            const uint32_t wrow = wb + (uint32_t)(((tap * 32 + g) * 16 + c * 4) * 4);
            #pragma unroll
            for (int nt = 0; nt < 4; nt++)
                lds4(w[0][nt], w[1][nt], w[2][nt], w[3][nt], wrow + nt * (8 * 64));
        };
        auto loadA = [&](int tap, uint32_t a[3][8]) {
            const int hk = tap / 3;
            const int tapoff = hk * 24 + (tap - 3 * hk);
            const uint32_t xrow = xb + (uint32_t)(((g + tapoff) * 16 + c * 4) * 4);
            #pragma unroll
            for (int mt = 0; mt < 3; mt++) {
                if (mt >= cnt) break;
                const int m0 = (wid + 12 * mt) * 16;
                lds4(a[mt][0], a[mt][1], a[mt][2], a[mt][3], xrow + m0 * 64);
                lds4(a[mt][4], a[mt][5], a[mt][6], a[mt][7], xrow + (m0 + 8) * 64);
            }
        };

        loadB(0, wreg[0]);
        loadA(0, areg[0]);

        #pragma unroll
        for (int tap = 0; tap < 9; tap++) {
            const int cb = tap & 1, nb = cb ^ 1;
            if (tap < 8) {
                loadB(tap + 1, wreg[nb]);
                loadA(tap + 1, areg[nb]);
            }
            #pragma unroll
            for (int mt = 0; mt < 3; mt++) {
                if (mt >= cnt) break;
                #pragma unroll
                for (int nt = 0; nt < 4; nt++)
                    MMA_TF32(acc[mt][nt],
                             areg[cb][mt][0], areg[cb][mt][4],
                             areg[cb][mt][1], areg[cb][mt][5],
                             wreg[cb][0][nt], wreg[cb][1][nt]);
                #pragma unroll
                for (int nt = 0; nt < 4; nt++)
                    MMA_TF32(acc[mt][nt],
                             areg[cb][mt][2], areg[cb][mt][6],
                             areg[cb][mt][3], areg[cb][mt][7],
                             wreg[cb][2][nt], wreg[cb][3][nt]);
            }
        }
        // no trailing __syncthreads
    }

    // ---- epilogue ----
    const float* bs = (const float*)(smem + OFF_BS);
    const int spat = l_out * 10648 + d_out * 484;
    for (int mt = 0; mt < cnt; mt++) {
        const int mb = (wid + 12 * mt) * 16 + g;
        #pragma unroll
        for (int hm = 0; hm < 2; hm++) {
            int m = mb + 8 * hm;
            int h = m / 24;
            int w = m - 24 * h;
            if (h < 22 && w < 22) {
                size_t pos = (size_t)spat + h * 22 + w;
                #pragma unroll
                for (int nt = 0; nt < 4; nt++) {
                    #pragma unroll
                    for (int hc = 0; hc < 2; hc++) {
                        int co = nt * 8 + 2 * c + hc;
                        out[(size_t)(n * 32 + co) * OUT_CO_STRIDE + pos] =
                            acc[mt][nt][hm * 2 + hc] + bs[co];
                    }
                }
            }
        }
    }
}

extern "C" void kernel_launch(void* const* d_in, const int* in_sizes, int n_in,
                              void* d_out, int out_size)
{
    const float* x = (const float*)d_in[0];
    const float* W = (const float*)d_in[1];
    const float* b = (const float*)d_in[2];
    float* out = (float*)d_out;

    dim3 pgrid(24, 32, 8);
    prep_x_kernel<<<pgrid, 256>>>(x);
    prep_w_kernel<<<162, 256>>>(W);

    cudaFuncSetAttribute(conv4d_mma_kernel,
                         cudaFuncAttributeMaxDynamicSharedMemorySize, SMEM_TOTAL);
    dim3 grid(22, 30, 8);   // (d_out, l_out, n)
    conv4d_mma_kernel<<<grid, 384, SMEM_TOTAL>>>(b, out);
}

// round 17
// speedup vs baseline: 1.1257x; 1.0302x over previous
#include <cuda_runtime.h>
#include <cstdint>

// Conv4D via mma.sync tf32 (portable sm_80+ PTX).
// x(8,16,32,24,24,24) NCLDHW * W(32,16,3,3,3,3) OILDHW -> out(8,32,30,22,22,22), +3*b.
//
// R17 = R16 (packed-m over 22x22 output, 31 m-tiles, SMSP-balanced map,
// triple-buffered staging, register-pipelined taps) with the R13 staging RACE
// FIXED: stage(s+2) is issued AFTER the slab barrier, so it writes buffer
// (s-1)%3 which every warp has provably finished reading (program order puts
// slab s-1 compute before the slab-s barrier).

#define XB 37120                   // 580 rows * 64B per x buffer
#define WB 18432                   // 288 rows * 64B per W buffer
#define OFF_X 0                    // 3 buffers
#define OFF_W (3 * XB)             // 111360, 3 buffers
#define OFF_BS (OFF_W + 3 * WB)    // 166656
#define SMEM_TOTAL (OFF_BS + 128)  // 166784

#define L_STRIDE 13824             // 24*24*24
#define OUT_CO_STRIDE 319440       // 30*22*22*22

__device__ uint32_t g_xp[56623104];    // [n][l][d][m=576][16 ci quad-interleaved]
__device__ uint32_t g_wp[41472];       // [s][tap][co][16 ci quad-interleaved]

static __device__ __forceinline__ uint32_t s2u(const void* p) {
    uint32_t a;
    asm("{ .reg .u64 t; cvta.to.shared.u64 t, %1; cvt.u32.u64 %0, t; }" : "=r"(a) : "l"(p));
    return a;
}
static __device__ __forceinline__ uint32_t tf32rn(float f) {
    uint32_t o;
    asm("cvt.rna.tf32.f32 %0, %1;" : "=r"(o) : "f"(f));
    return o;
}
static __device__ __forceinline__ void cp16(uint32_t dst, const void* src) {
    asm volatile("cp.async.cg.shared.global [%0], [%1], 16;" :: "r"(dst), "l"(src) : "memory");
}
static __device__ __forceinline__ void lds4(uint32_t& r0, uint32_t& r1, uint32_t& r2, uint32_t& r3, uint32_t a) {
    asm volatile("ld.shared.v4.u32 {%0,%1,%2,%3}, [%4];" : "=r"(r0), "=r"(r1), "=r"(r2), "=r"(r3) : "r"(a));
}

#define MMA_TF32(d, a0, a1, a2, a3, b0, b1) \
    asm volatile("mma.sync.aligned.m16n8k8.row.col.f32.tf32.tf32.f32 " \
        "{%0,%1,%2,%3}, {%4,%5,%6,%7}, {%8,%9}, {%0,%1,%2,%3};" \
        : "+f"((d)[0]), "+f"((d)[1]), "+f"((d)[2]), "+f"((d)[3]) \
        : "r"(a0), "r"(a1), "r"(a2), "r"(a3), "r"(b0), "r"(b1))

// ---- prepass: x -> tf32 bits; within-row order pos = (ci%4)*4 + ci/4 ----
__global__ __launch_bounds__(256)
void prep_x_kernel(const float* __restrict__ x) {
    const int d = blockIdx.x, l = blockIdx.y, n = blockIdx.z;
    const int tid = threadIdx.x;
    const size_t src0 = ((size_t)(n * 16) * 32 + l) * L_STRIDE + d * 576;
    uint32_t* dst0 = g_xp + (((size_t)(n * 32 + l) * 24 + d) * 576) * 16;
    for (int m = tid; m < 576; m += 256) {
        uint32_t v[16];
        #pragma unroll
        for (int ci = 0; ci < 16; ci++)
            v[(ci & 3) * 4 + (ci >> 2)] = tf32rn(x[src0 + (size_t)ci * (32 * L_STRIDE) + m]);
        uint32_t* dr = dst0 + m * 16;
        #pragma unroll
        for (int q = 0; q < 4; q++)
            *(uint4*)(dr + q * 4) = make_uint4(v[q*4], v[q*4+1], v[q*4+2], v[q*4+3]);
    }
}

// ---- prepass: W -> tf32 bits, [s][tap][co][pos], ci = (pos>>2) + (pos&3)*4 ----
__global__ __launch_bounds__(256)
void prep_w_kernel(const float* __restrict__ W) {
    int e = blockIdx.x * 256 + threadIdx.x;     // 0..41471
    int pos = e & 15;
    int co  = (e >> 4) & 31;
    int t9  = e >> 9;                            // s*9+tap
    int s   = t9 / 9, tap = t9 - 9 * s;
    int lk = s / 3,  dk = s - 3 * lk;
    int hk = tap / 3, wk = tap - 3 * hk;
    int ci = (pos >> 2) + (pos & 3) * 4;
    g_wp[e] = tf32rn(W[(size_t)(co * 16 + ci) * 81 + lk * 27 + dk * 9 + hk * 3 + wk]);
}

extern __shared__ char smem[];

__global__ __launch_bounds__(384)
void conv4d_mma_kernel(const float* __restrict__ b, float* __restrict__ out)
{
    const int d_out = blockIdx.x;   // 0..21
    const int l_out = blockIdx.y;   // 0..29
    const int n     = blockIdx.z;   // 0..7
    const int tid   = threadIdx.x;
    const int wid   = tid >> 5;     // 0..11
    const int lid   = tid & 31;
    const int c     = lid & 3;
    const int g     = lid >> 2;
    const uint32_t sb = s2u(smem);

    if (tid < 32) ((float*)(smem + OFF_BS))[tid] = 3.0f * b[tid];

    // stage slab s into buffer s%3 (x and W, one commit group)
    auto stage = [&](int s) {
        const int bi = s % 3;
        const int lk = s / 3, dk = s - 3 * lk;
        const uint32_t xo = sb + OFF_X + bi * XB;
        const uint32_t wo = sb + OFF_W + bi * WB;
        const uint32_t* xs = g_xp + (((size_t)(n * 32 + (l_out + lk)) * 24 + (d_out + dk)) * 576) * 16;
        #pragma unroll
        for (int j6 = 0; j6 < 6; j6++) {
            int j = tid + j6 * 384;              // 0..2303
            cp16(xo + (uint32_t)(j * 16), xs + (size_t)j * 4);
        }
        const uint32_t* wsrc = g_wp + s * 4608;
        #pragma unroll
        for (int j3 = 0; j3 < 3; j3++) {
            int j = tid + j3 * 384;              // 0..1151
            cp16(wo + (uint32_t)(j * 16), wsrc + j * 4);
        }
        asm volatile("cp.async.commit_group;" ::: "memory");
    };

    // packed-m tile map: 31 tiles, t = wid + 12*mt; SMSP tile loads 8/8/8/7
    const int cnt = (wid < 7) ? 3 : 2;

    // per-lane x-row byte offsets (kernel-constant): row(p) = p + 2*(p/22)
    uint32_t ra0[3], ra1[3];
    #pragma unroll
    for (int mt = 0; mt < 3; mt++) {
        int m0 = (wid + 12 * mt) * 16;
        int p0 = m0 + g;      if (p0 > 483) p0 = 483;
        int p1 = m0 + g + 8;  if (p1 > 483) p1 = 483;
        int r0 = p0 + 2 * (p0 / 22);
        int r1 = p1 + 2 * (p1 / 22);
        ra0[mt] = (uint32_t)(r0 * 64 + c * 16);
        ra1[mt] = (uint32_t)(r1 * 64 + c * 16);
    }

    float acc[3][4][4];
    #pragma unroll
    for (int mt = 0; mt < 3; mt++)
        #pragma unroll
        for (int nt = 0; nt < 4; nt++)
            #pragma unroll
            for (int q = 0; q < 4; q++)
                acc[mt][nt][q] = 0.0f;

    stage(0);
    stage(1);

    uint32_t wreg[2][4][4];   // [buf][q][nt]
    uint32_t areg[2][3][8];   // [buf][mt][l0..l3,h0..h3]

    for (int s = 0; s < 9; s++) {
        const int bi = s % 3;
        // wait for slab s's staging (allow 1 group in flight), THEN barrier,
        // THEN issue stage(s+2): it writes buf (s-1)%3, finished by all warps.
        if (s < 8) {
            asm volatile("cp.async.wait_group 1;" ::: "memory");
        } else {
            asm volatile("cp.async.wait_group 0;" ::: "memory");
        }
        __syncthreads();
        if (s < 7) stage(s + 2);

        const uint32_t xb = sb + OFF_X + bi * XB;
        const uint32_t wb = sb + OFF_W + bi * WB;

        auto loadB = [&](int tap, uint32_t w[4][4]) {
            const uint32_t wrow = wb + (uint32_t)(((tap * 32 + g) * 16 + c * 4) * 4);
            #pragma unroll
            for (int nt = 0; nt < 4; nt++)
                lds4(w[0][nt], w[1][nt], w[2][nt], w[3][nt], wrow + nt * (8 * 64));
        };
        auto loadA = [&](int tap, uint32_t a[3][8]) {
            const int hk = tap / 3;
            const uint32_t tb = xb + (uint32_t)((hk * 24 + (tap - 3 * hk)) * 64);
            #pragma unroll
            for (int mt = 0; mt < 3; mt++) {
                if (mt >= cnt) break;
                lds4(a[mt][0], a[mt][1], a[mt][2], a[mt][3], tb + ra0[mt]);
                lds4(a[mt][4], a[mt][5], a[mt][6], a[mt][7], tb + ra1[mt]);
            }
        };

        loadB(0, wreg[0]);
        loadA(0, areg[0]);

        #pragma unroll
        for (int tap = 0; tap < 9; tap++) {
            const int cb = tap & 1, nb = cb ^ 1;
            if (tap < 8) {
                loadB(tap + 1, wreg[nb]);
                loadA(tap + 1, areg[nb]);
            }
            #pragma unroll
            for (int mt = 0; mt < 3; mt++) {
                if (mt >= cnt) break;
                #pragma unroll
                for (int nt = 0; nt < 4; nt++)
                    MMA_TF32(acc[mt][nt],
                             areg[cb][mt][0], areg[cb][mt][4],
                             areg[cb][mt][1], areg[cb][mt][5],
                             wreg[cb][0][nt], wreg[cb][1][nt]);
                #pragma unroll
                for (int nt = 0; nt < 4; nt++)
                    MMA_TF32(acc[mt][nt],
                             areg[cb][mt][2], areg[cb][mt][6],
                             areg[cb][mt][3], areg[cb][mt][7],
                             wreg[cb][2][nt], wreg[cb][3][nt]);
            }
        }
        // no trailing __syncthreads (triple buffer + post-barrier staging)
    }

    // ---- epilogue: packed m == output position ----
    const float* bs = (const float*)(smem + OFF_BS);
    const int spat = l_out * 10648 + d_out * 484;
    for (int mt = 0; mt < cnt; mt++) {
        const int mb = (wid + 12 * mt) * 16 + g;
        #pragma unroll
        for (int hm = 0; hm < 2; hm++) {
            int p = mb + 8 * hm;
            if (p < 484) {
                size_t pos = (size_t)spat + p;
                #pragma unroll
                for (int nt = 0; nt < 4; nt++) {
                    #pragma unroll
                    for (int hc = 0; hc < 2; hc++) {
                        int co = nt * 8 + 2 * c + hc;
                        out[(size_t)(n * 32 + co) * OUT_CO_STRIDE + pos] =
                            acc[mt][nt][hm * 2 + hc] + bs[co];
                    }
                }
            }
        }
    }
}

extern "C" void kernel_launch(void* const* d_in, const int* in_sizes, int n_in,
                              void* d_out, int out_size)
{
    const float* x = (const float*)d_in[0];
    const float* W = (const float*)d_in[1];
    const float* b = (const float*)d_in[2];
    float* out = (float*)d_out;

    dim3 pgrid(24, 32, 8);
    prep_x_kernel<<<pgrid, 256>>>(x);
    prep_w_kernel<<<162, 256>>>(W);

    cudaFuncSetAttribute(conv4d_mma_kernel,
                         cudaFuncAttributeMaxDynamicSharedMemorySize, SMEM_TOTAL);
    dim3 grid(22, 30, 8);   // (d_out, l_out, n)
    conv4d_mma_kernel<<<grid, 384, SMEM_TOTAL>>>(b, out);
}